// round 7
// baseline (speedup 1.0000x reference)
#include <cuda_runtime.h>
#include <cuda_bf16.h>
#include <math.h>
#include <stdint.h>

// ---------------------------------------------------------------------------
// LNN — collapsed leaky-integrator MLP on tensor cores via mma.sync (bf16),
// fp32 emulated with 3-term hi/lo split: A*B ~= Ahi*Bhi + Alo*Bhi + Ahi*Blo.
// fp32->bf16 hi/lo conversion fused into the GEMM smem loaders (traffic-
// neutral: fp32 4B/el == hi+lo bf16 4B/el); intermediates stay fp32.
//
//   d1    = relu(x @ W1^T + b1)            GEMM1 (epilogue: relu, fp32 out)
//   s2acc = scan(d1 @ W2^T, b2)            GEMM2 (epilogue: T-step scan)
//   part  = split-K s2acc @ W3^T           GEMM3 (epilogue: raw fp32 partials)
//   out   = (1-b3^T) b3 + sum_z part[z]    reduce
// ---------------------------------------------------------------------------

#define MODE_RELU 0
#define MODE_SCAN 1
#define MODE_PART 2
#define KSPLIT 2

typedef __nv_bfloat16 bf16;

// ----- device scratch (no allocations allowed) -----
#define AL __align__(256)
__device__ AL float g_d1 [1024*4096];
__device__ AL float g_s2 [1024*4096];
__device__ AL float g_part[KSPLIT*1024*1024];

__device__ __forceinline__ float sigmoid_acc(float v) { return 1.0f / (1.0f + expf(-v)); }

__device__ __forceinline__ uint32_t smem_u32(const void* p) {
    uint32_t a;
    asm("{ .reg .u64 t; cvta.to.shared.u64 t, %1; cvt.u32.u64 %0, t; }" : "=r"(a) : "l"(p));
    return a;
}

__device__ __forceinline__ void ldsm_x4(uint32_t* r, uint32_t addr) {
    asm volatile("ldmatrix.sync.aligned.m8n8.x4.shared.b16 {%0,%1,%2,%3}, [%4];"
                 : "=r"(r[0]), "=r"(r[1]), "=r"(r[2]), "=r"(r[3]) : "r"(addr));
}

__device__ __forceinline__ void mma_bf16(float* c, const uint32_t* a, const uint32_t* b) {
    asm volatile("mma.sync.aligned.m16n8k16.row.col.f32.bf16.bf16.f32 "
                 "{%0,%1,%2,%3}, {%4,%5,%6,%7}, {%8,%9}, {%0,%1,%2,%3};"
                 : "+f"(c[0]), "+f"(c[1]), "+f"(c[2]), "+f"(c[3])
                 : "r"(a[0]), "r"(a[1]), "r"(a[2]), "r"(a[3]), "r"(b[0]), "r"(b[1]));
}

// SW64-style swizzle: row stride 64B, 16B chunk c xored by (r>>1)&3.
__device__ __forceinline__ uint32_t sw_off(int r, int c) {
    return (uint32_t)(r * 64 + ((c ^ ((r >> 1) & 3)) << 4));
}

// split 8 fp32 -> packed bf16 hi (uint4) and lo (uint4)
__device__ __forceinline__ void split8(const float4 v0, const float4 v1,
                                       uint4& hp, uint4& lp)
{
    float v[8] = {v0.x, v0.y, v0.z, v0.w, v1.x, v1.y, v1.z, v1.w};
    uint32_t hw[8], lw[8];
#pragma unroll
    for (int q = 0; q < 8; q++) {
        bf16 h = __float2bfloat16(v[q]);
        bf16 l = __float2bfloat16(v[q] - __bfloat162float(h));
        hw[q] = __bfloat16_as_ushort(h);
        lw[q] = __bfloat16_as_ushort(l);
    }
    hp.x = hw[0] | (hw[1] << 16); hp.y = hw[2] | (hw[3] << 16);
    hp.z = hw[4] | (hw[5] << 16); hp.w = hw[6] | (hw[7] << 16);
    lp.x = lw[0] | (lw[1] << 16); lp.y = lw[2] | (lw[3] << 16);
    lp.z = lw[4] | (lw[5] << 16); lp.w = lw[6] | (lw[7] << 16);
}

// ---------------------------------------------------------------------------
// Tensor-core GEMM:  C[M,N] = A[M,K] @ B[N,K]^T, fp32 in/out, BM=BN=128,
// BK=32, 8 warps (4Mx2N), warp tile 32x64, mma.m16n8k16 bf16 x3 terms.
// Double-buffered smem, conversion fused into loader.
// ---------------------------------------------------------------------------
__global__ void __launch_bounds__(256)
tc_gemm(const float* __restrict__ Af, const float* __restrict__ Bf,
        const float* __restrict__ bias, float* __restrict__ Cf,
        int M, int N, int K, int lda, int mode,
        const float* __restrict__ b_taus, const int* __restrict__ Tp)
{
    extern __shared__ __align__(128) char smem[];
    const uint32_t sb = smem_u32(smem);
    // per stage: AHI 8K | ALO 8K | BHI 8K | BLO 8K  = 32 KB; two stages
    constexpr uint32_t STG = 32768;
    constexpr uint32_t S_AHI = 0, S_ALO = 8192, S_BHI = 16384, S_BLO = 24576;

    const int tid = threadIdx.x;
    const int wid = tid >> 5;
    const int lid = tid & 31;
    const int warpM = wid & 3;
    const int warpN = wid >> 2;

    const int m0 = blockIdx.y * 128;
    const int n0 = blockIdx.x * 128;
    const int kbase = blockIdx.z * K;   // split-K slab

    // loader: chunk positions u = tid, tid+256 per tile; row = u>>2, cg = u&3
    const int r0 = tid >> 2, c0 = tid & 3;
    const size_t step64 = (size_t)64 * lda;
    const float* gA = Af + (size_t)(m0 + r0) * lda + kbase + c0 * 8;
    const float* gB = Bf + (size_t)(n0 + r0) * lda + kbase + c0 * 8;
    const uint32_t so0 = sw_off(r0, c0), so1 = sw_off(r0 + 64, c0);

    // ldmatrix per-thread addressing
    const int id = lid >> 3, rin = lid & 7;
    const int arow = warpM * 32 + (id & 1) * 8 + rin;
    const int acol = (id >> 1);
    const int brow = warpN * 64 + (id >> 1) * 8 + rin;
    const int bcol = (id & 1);

    float acc[2][8][4];
#pragma unroll
    for (int mt = 0; mt < 2; mt++)
#pragma unroll
        for (int nf = 0; nf < 8; nf++)
#pragma unroll
            for (int q = 0; q < 4; q++) acc[mt][nf][q] = 0.0f;

    const int NCH = K / 32;
    float4 pA[2][2], pB[2][2];

    auto LOADCH = [&](int kc) {
        pA[0][0] = *(const float4*)(gA + kc);
        pA[0][1] = *(const float4*)(gA + kc + 4);
        pA[1][0] = *(const float4*)(gA + kc + step64);
        pA[1][1] = *(const float4*)(gA + kc + step64 + 4);
        pB[0][0] = *(const float4*)(gB + kc);
        pB[0][1] = *(const float4*)(gB + kc + 4);
        pB[1][0] = *(const float4*)(gB + kc + step64);
        pB[1][1] = *(const float4*)(gB + kc + step64 + 4);
    };
    auto STORECH = [&](int s) {
        char* base = smem + s * STG;
        uint4 hp, lp;
        split8(pA[0][0], pA[0][1], hp, lp);
        *(uint4*)(base + S_AHI + so0) = hp; *(uint4*)(base + S_ALO + so0) = lp;
        split8(pA[1][0], pA[1][1], hp, lp);
        *(uint4*)(base + S_AHI + so1) = hp; *(uint4*)(base + S_ALO + so1) = lp;
        split8(pB[0][0], pB[0][1], hp, lp);
        *(uint4*)(base + S_BHI + so0) = hp; *(uint4*)(base + S_BLO + so0) = lp;
        split8(pB[1][0], pB[1][1], hp, lp);
        *(uint4*)(base + S_BHI + so1) = hp; *(uint4*)(base + S_BLO + so1) = lp;
    };

    LOADCH(0);
    STORECH(0);
    __syncthreads();

    for (int ch = 0; ch < NCH; ch++) {
        if (ch + 1 < NCH) LOADCH((ch + 1) * 32);
        const uint32_t bufb = sb + (uint32_t)(ch & 1) * STG;

#pragma unroll
        for (int kk = 0; kk < 2; kk++) {
            uint32_t ah[2][4], al[2][4];
#pragma unroll
            for (int mt = 0; mt < 2; mt++) {
                uint32_t ao = sw_off(arow + mt * 16, acol + kk * 2);
                ldsm_x4(ah[mt], bufb + S_AHI + ao);
                ldsm_x4(al[mt], bufb + S_ALO + ao);
            }
            uint32_t bh[4][4], bl[4][4];
#pragma unroll
            for (int nt2 = 0; nt2 < 4; nt2++) {
                uint32_t bo = sw_off(brow + nt2 * 16, bcol + kk * 2);
                ldsm_x4(bh[nt2], bufb + S_BHI + bo);
                ldsm_x4(bl[nt2], bufb + S_BLO + bo);
            }
#pragma unroll
            for (int mt = 0; mt < 2; mt++)
#pragma unroll
                for (int nt2 = 0; nt2 < 4; nt2++)
#pragma unroll
                    for (int h = 0; h < 2; h++) {
                        float* c = acc[mt][nt2 * 2 + h];
                        mma_bf16(c, ah[mt], &bh[nt2][h * 2]);   // hi*hi
                        mma_bf16(c, al[mt], &bh[nt2][h * 2]);   // lo*hi
                        mma_bf16(c, ah[mt], &bl[nt2][h * 2]);   // hi*lo
                    }
        }
        if (ch + 1 < NCH) {
            STORECH((ch + 1) & 1);
            __syncthreads();
        }
    }

    // ---- epilogue (register fragments, fp32 outputs) ----
    float beta1 = 0.f, beta2 = 0.f, wt0 = 0.f, invb3 = 0.f, om2 = 0.f;
    int T = 0;
    if (mode == MODE_SCAN) {
        beta1 = sigmoid_acc(b_taus[0]);
        beta2 = sigmoid_acc(b_taus[1]);
        float beta3 = sigmoid_acc(b_taus[2]);
        T     = *Tp;
        invb3 = 1.0f / beta3;
        om2   = 1.0f - beta2;
        wt0   = (1.0f - beta3) * powf(beta3, (float)(T - 1));
    }

    const int mrow = m0 + warpM * 32 + (lid >> 2);
    const int ncol = n0 + warpN * 64 + (lid & 3) * 2;
    float* Cz = (mode == MODE_PART) ? Cf + (size_t)blockIdx.z * M * N : Cf;

#pragma unroll
    for (int mt = 0; mt < 2; mt++) {
#pragma unroll
        for (int nf = 0; nf < 8; nf++) {
            const int col = ncol + nf * 8;
#pragma unroll
            for (int pair = 0; pair < 2; pair++) {
                const int row = mrow + mt * 16 + pair * 8;
                float v0 = acc[mt][nf][pair * 2 + 0];
                float v1 = acc[mt][nf][pair * 2 + 1];
                size_t base = (size_t)row * N + col;

                if (mode == MODE_PART) {
                    *(float2*)(Cz + base) = make_float2(v0, v1);
                    continue;
                }
                float bv0 = __ldg(&bias[col]), bv1 = __ldg(&bias[col + 1]);
                float o0, o1;
                if (mode == MODE_RELU) {
                    o0 = fmaxf(v0 + bv0, 0.0f);
                    o1 = fmaxf(v1 + bv1, 0.0f);
                } else {
                    float s20 = 0.f, a0 = 0.f, s21 = 0.f, a1 = 0.f;
                    float bp = beta1, wt = wt0;
                    for (int t = 0; t < T; t++) {
                        float c1m = 1.0f - bp;
                        float d0 = fmaxf(fmaf(c1m, v0, bv0), 0.0f);
                        float d1 = fmaxf(fmaf(c1m, v1, bv1), 0.0f);
                        s20 = fmaf(beta2, s20, om2 * d0);
                        s21 = fmaf(beta2, s21, om2 * d1);
                        a0 = fmaf(wt, s20, a0);
                        a1 = fmaf(wt, s21, a1);
                        bp *= beta1;
                        wt *= invb3;
                    }
                    o0 = a0; o1 = a1;
                }
                *(float2*)(Cz + base) = make_float2(o0, o1);
            }
        }
    }
}

// out[i] = (1 - beta3^T) * b3[i % N] + sum_z part[z][i]
__global__ void __launch_bounds__(256)
reduce_out(const float* __restrict__ part, const float* __restrict__ b3,
           float* __restrict__ out, int total, int N,
           const float* __restrict__ b_taus, const int* __restrict__ Tp)
{
    int i = (blockIdx.x * blockDim.x + threadIdx.x) * 4;
    if (i >= total) return;
    float beta3  = sigmoid_acc(b_taus[2]);
    float bscale = 1.0f - powf(beta3, (float)(*Tp));
    float4 bb = *(const float4*)(b3 + (i % N));
    float4 s  = make_float4(bscale * bb.x, bscale * bb.y, bscale * bb.z, bscale * bb.w);
#pragma unroll
    for (int z = 0; z < KSPLIT; z++) {
        float4 p = *(const float4*)(part + (size_t)z * total + i);
        s.x += p.x; s.y += p.y; s.z += p.z; s.w += p.w;
    }
    *(float4*)(out + i) = s;
}

extern "C" void kernel_launch(void* const* d_in, const int* in_sizes, int n_in,
                              void* d_out, int out_size)
{
    const float* x     = (const float*)d_in[0];
    const float* W1    = (const float*)d_in[1];
    const float* b1    = (const float*)d_in[2];
    const float* W2    = (const float*)d_in[3];
    const float* b2    = (const float*)d_in[4];
    const float* W3    = (const float*)d_in[5];
    const float* b3    = (const float*)d_in[6];
    const float* btaus = (const float*)d_in[7];
    const int*   Tp    = (const int*)d_in[8];

    const int H1    = in_sizes[2];
    const int D_IN  = in_sizes[1] / H1;
    const int B     = in_sizes[0] / D_IN;
    const int H2    = in_sizes[4];
    const int D_OUT = in_sizes[6];

    float *d1, *s2, *part;
    cudaGetSymbolAddress((void**)&d1,   g_d1);
    cudaGetSymbolAddress((void**)&s2,   g_s2);
    cudaGetSymbolAddress((void**)&part, g_part);

    float* out = (float*)d_out;

    const int SMEM = 2 * 32768;
    static int attr_done = 0;
    if (!attr_done) {
        cudaFuncSetAttribute(tc_gemm, cudaFuncAttributeMaxDynamicSharedMemorySize, SMEM);
        attr_done = 1;
    }

    // 1) d1 = relu(x @ W1^T + b1)                     [B, H1]
    {
        dim3 grid(H1 / 128, B / 128, 1);
        tc_gemm<<<grid, 256, SMEM>>>(x, W1, b1, d1, B, H1, D_IN, D_IN,
                                     MODE_RELU, btaus, Tp);
    }
    // 2) s2 = scan(d1 @ W2^T, b2)                     [B, H2]
    {
        dim3 grid(H2 / 128, B / 128, 1);
        tc_gemm<<<grid, 256, SMEM>>>(d1, W2, b2, s2, B, H2, H1, H1,
                                     MODE_SCAN, btaus, Tp);
    }
    // 3) split-K partials of s2 @ W3^T                [KSPLIT][B, D_OUT]
    {
        dim3 grid(D_OUT / 128, B / 128, KSPLIT);
        tc_gemm<<<grid, 256, SMEM>>>(s2, W3, nullptr, part, B, D_OUT,
                                     H2 / KSPLIT, H2, MODE_PART, btaus, Tp);
    }
    // 4) out = (1-b3^T) b3 + sum partials             [B, D_OUT]
    {
        int total = B * D_OUT;
        reduce_out<<<(total / 4 + 255) / 256, 256>>>(part, b3, out, total, D_OUT, btaus, Tp);
    }
    (void)n_in; (void)out_size;
}

// round 9
// speedup vs baseline: 1.2987x; 1.2987x over previous
#include <cuda_runtime.h>
#include <cuda_bf16.h>
#include <math.h>
#include <stdint.h>

// ---------------------------------------------------------------------------
// LNN — collapsed leaky-integrator MLP on tensor cores via mma.sync (bf16),
// fp32 emulated with 3-term hi/lo split: A*B ~= Ahi*Bhi + Alo*Bhi + Ahi*Blo.
// Standalone convert kernels (fast, memory-bound); GEMM loader moves bf16
// only, via cp.async double buffering (one barrier per K-chunk).
//
//   d1    = relu(x @ W1^T + b1)            GEMM1 (epilogue: relu + bf16-split)
//   s2acc = scan(d1 @ W2^T, b2)            GEMM2 (epilogue: T-step scan + split)
//   part  = split-K s2acc @ W3^T           GEMM3 (epilogue: raw fp32 partials)
//   out   = (1-b3^T) b3 + sum_z part[z]    reduce
// ---------------------------------------------------------------------------

#define MODE_RELU 0
#define MODE_SCAN 1
#define MODE_PART 2
#define KSPLIT 2

typedef __nv_bfloat16 bf16;

// ----- device scratch (no allocations allowed) -----
#define AL __align__(256)
__device__ AL bf16 g_xhi [1024*2048], g_xlo [1024*2048];
__device__ AL bf16 g_w1hi[4096*2048], g_w1lo[4096*2048];
__device__ AL bf16 g_w2hi[4096*4096], g_w2lo[4096*4096];
__device__ AL bf16 g_w3hi[1024*4096], g_w3lo[1024*4096];
__device__ AL bf16 g_d1hi[1024*4096], g_d1lo[1024*4096];
__device__ AL bf16 g_s2hi[1024*4096], g_s2lo[1024*4096];
__device__ AL float g_part[KSPLIT*1024*1024];

__device__ __forceinline__ float sigmoid_acc(float v) { return 1.0f / (1.0f + expf(-v)); }

__device__ __forceinline__ uint32_t smem_u32(const void* p) {
    uint32_t a;
    asm("{ .reg .u64 t; cvta.to.shared.u64 t, %1; cvt.u32.u64 %0, t; }" : "=r"(a) : "l"(p));
    return a;
}

__device__ __forceinline__ void ldsm_x4(uint32_t* r, uint32_t addr) {
    asm volatile("ldmatrix.sync.aligned.m8n8.x4.shared.b16 {%0,%1,%2,%3}, [%4];"
                 : "=r"(r[0]), "=r"(r[1]), "=r"(r[2]), "=r"(r[3]) : "r"(addr));
}

__device__ __forceinline__ void mma_bf16(float* c, const uint32_t* a, const uint32_t* b) {
    asm volatile("mma.sync.aligned.m16n8k16.row.col.f32.bf16.bf16.f32 "
                 "{%0,%1,%2,%3}, {%4,%5,%6,%7}, {%8,%9}, {%0,%1,%2,%3};"
                 : "+f"(c[0]), "+f"(c[1]), "+f"(c[2]), "+f"(c[3])
                 : "r"(a[0]), "r"(a[1]), "r"(a[2]), "r"(a[3]), "r"(b[0]), "r"(b[1]));
}

__device__ __forceinline__ void cpa16(uint32_t dst, const void* src) {
    asm volatile("cp.async.cg.shared.global [%0], [%1], 16;"
                 :: "r"(dst), "l"(src) : "memory");
}
#define CP_COMMIT() asm volatile("cp.async.commit_group;" ::: "memory")
#define CP_WAIT0()  asm volatile("cp.async.wait_group 0;" ::: "memory")

// SW64-style swizzle: row stride 64B, 16B chunk c xored by (r>>1)&3.
__device__ __forceinline__ uint32_t sw_off(int r, int c) {
    return (uint32_t)(r * 64 + ((c ^ ((r >> 1) & 3)) << 4));
}

// ----- fp32 -> bf16 hi/lo split (8 elems/thread) -----
__global__ void __launch_bounds__(256)
convert_split(const float* __restrict__ src, bf16* __restrict__ hi,
              bf16* __restrict__ lo, int n)
{
    int i = (blockIdx.x * 256 + threadIdx.x) * 8;
    if (i >= n) return;
    float4 v0 = *(const float4*)(src + i);
    float4 v1 = *(const float4*)(src + i + 4);
    float v[8] = {v0.x, v0.y, v0.z, v0.w, v1.x, v1.y, v1.z, v1.w};
    uint32_t hw[8], lw[8];
#pragma unroll
    for (int q = 0; q < 8; q++) {
        bf16 h = __float2bfloat16(v[q]);
        bf16 l = __float2bfloat16(v[q] - __bfloat162float(h));
        hw[q] = __bfloat16_as_ushort(h);
        lw[q] = __bfloat16_as_ushort(l);
    }
    uint4 hp, lp;
    hp.x = hw[0] | (hw[1] << 16); hp.y = hw[2] | (hw[3] << 16);
    hp.z = hw[4] | (hw[5] << 16); hp.w = hw[6] | (hw[7] << 16);
    lp.x = lw[0] | (lw[1] << 16); lp.y = lw[2] | (lw[3] << 16);
    lp.z = lw[4] | (lw[5] << 16); lp.w = lw[6] | (lw[7] << 16);
    *(uint4*)(hi + i) = hp;
    *(uint4*)(lo + i) = lp;
}

// ---------------------------------------------------------------------------
// Tensor-core GEMM:  C[M,N] = A[M,K] @ B[N,K]^T, BM=BN=128, BK=32, 8 warps
// (4Mx2N), warp tile 32x64. mma.m16n8k16 bf16 x3 terms, fp32 acc.
// cp.async double-buffered smem (2 x 32 KB), one barrier per K-chunk.
// ---------------------------------------------------------------------------
__global__ void __launch_bounds__(256)
tc_gemm(const bf16* __restrict__ Ahi, const bf16* __restrict__ Alo,
        const bf16* __restrict__ Bhi, const bf16* __restrict__ Blo,
        const float* __restrict__ bias, float* __restrict__ Cf,
        bf16* __restrict__ OutHi, bf16* __restrict__ OutLo,
        int M, int N, int K, int lda, int mode,
        const float* __restrict__ b_taus, const int* __restrict__ Tp)
{
    extern __shared__ __align__(128) char smem[];
    const uint32_t sb = smem_u32(smem);
    constexpr uint32_t STG = 32768;
    constexpr uint32_t S_AHI = 0, S_ALO = 8192, S_BHI = 16384, S_BLO = 24576;

    const int tid = threadIdx.x;
    const int wid = tid >> 5;
    const int lid = tid & 31;
    const int warpM = wid & 3;
    const int warpN = wid >> 2;

    const int m0 = blockIdx.y * 128;
    const int n0 = blockIdx.x * 128;
    const int kbase = blockIdx.z * K;   // split-K slab

    // loader: 16B chunks; row = tid>>2 (and +64), chunk col = tid&3
    const int r0 = tid >> 2, c0 = tid & 3;
    const size_t step64 = (size_t)64 * lda;
    const bf16* gAh = Ahi + (size_t)(m0 + r0) * lda + kbase + c0 * 8;
    const bf16* gAl = Alo + (size_t)(m0 + r0) * lda + kbase + c0 * 8;
    const bf16* gBh = Bhi + (size_t)(n0 + r0) * lda + kbase + c0 * 8;
    const bf16* gBl = Blo + (size_t)(n0 + r0) * lda + kbase + c0 * 8;
    const uint32_t so0 = sw_off(r0, c0), so1 = sw_off(r0 + 64, c0);

    // ldmatrix per-thread addressing
    const int id = lid >> 3, rin = lid & 7;
    const int arow = warpM * 32 + (id & 1) * 8 + rin;
    const int acol = (id >> 1);
    const int brow = warpN * 64 + (id >> 1) * 8 + rin;
    const int bcol = (id & 1);

    float acc[2][8][4];
#pragma unroll
    for (int mt = 0; mt < 2; mt++)
#pragma unroll
        for (int nf = 0; nf < 8; nf++)
#pragma unroll
            for (int q = 0; q < 4; q++) acc[mt][nf][q] = 0.0f;

    const int NCH = K / 32;

    auto ISSUE = [&](int ch) {
        const int kc = ch * 32;
        const uint32_t dst = sb + (uint32_t)(ch & 1) * STG;
        cpa16(dst + S_AHI + so0, gAh + kc);
        cpa16(dst + S_AHI + so1, gAh + kc + step64);
        cpa16(dst + S_ALO + so0, gAl + kc);
        cpa16(dst + S_ALO + so1, gAl + kc + step64);
        cpa16(dst + S_BHI + so0, gBh + kc);
        cpa16(dst + S_BHI + so1, gBh + kc + step64);
        cpa16(dst + S_BLO + so0, gBl + kc);
        cpa16(dst + S_BLO + so1, gBl + kc + step64);
        CP_COMMIT();
    };

    ISSUE(0);
    CP_WAIT0();
    __syncthreads();

    for (int ch = 0; ch < NCH; ch++) {
        if (ch + 1 < NCH) ISSUE(ch + 1);
        const uint32_t bufb = sb + (uint32_t)(ch & 1) * STG;

#pragma unroll
        for (int kk = 0; kk < 2; kk++) {
            uint32_t ah[2][4], al[2][4];
#pragma unroll
            for (int mt = 0; mt < 2; mt++) {
                uint32_t ao = sw_off(arow + mt * 16, acol + kk * 2);
                ldsm_x4(ah[mt], bufb + S_AHI + ao);
                ldsm_x4(al[mt], bufb + S_ALO + ao);
            }
            uint32_t bh[4][4], bl[4][4];
#pragma unroll
            for (int nt2 = 0; nt2 < 4; nt2++) {
                uint32_t bo = sw_off(brow + nt2 * 16, bcol + kk * 2);
                ldsm_x4(bh[nt2], bufb + S_BHI + bo);
                ldsm_x4(bl[nt2], bufb + S_BLO + bo);
            }
#pragma unroll
            for (int mt = 0; mt < 2; mt++)
#pragma unroll
                for (int nt2 = 0; nt2 < 4; nt2++)
#pragma unroll
                    for (int h = 0; h < 2; h++) {
                        float* c = acc[mt][nt2 * 2 + h];
                        mma_bf16(c, ah[mt], &bh[nt2][h * 2]);   // hi*hi
                        mma_bf16(c, al[mt], &bh[nt2][h * 2]);   // lo*hi
                        mma_bf16(c, ah[mt], &bl[nt2][h * 2]);   // hi*lo
                    }
        }
        if (ch + 1 < NCH) {
            CP_WAIT0();
            __syncthreads();
        }
    }

    // ---- epilogue (register fragments) ----
    float beta1 = 0.f, beta2 = 0.f, wt0 = 0.f, invb3 = 0.f, om2 = 0.f;
    int T = 0;
    if (mode == MODE_SCAN) {
        beta1 = sigmoid_acc(b_taus[0]);
        beta2 = sigmoid_acc(b_taus[1]);
        float beta3 = sigmoid_acc(b_taus[2]);
        T     = *Tp;
        invb3 = 1.0f / beta3;
        om2   = 1.0f - beta2;
        wt0   = (1.0f - beta3) * powf(beta3, (float)(T - 1));
    }

    const int mrow = m0 + warpM * 32 + (lid >> 2);
    const int ncol = n0 + warpN * 64 + (lid & 3) * 2;

#pragma unroll
    for (int mt = 0; mt < 2; mt++) {
#pragma unroll
        for (int nf = 0; nf < 8; nf++) {
            const int col = ncol + nf * 8;
#pragma unroll
            for (int pair = 0; pair < 2; pair++) {
                const int row = mrow + mt * 16 + pair * 8;
                float v0 = acc[mt][nf][pair * 2 + 0];
                float v1 = acc[mt][nf][pair * 2 + 1];
                size_t base = (size_t)row * N + col;

                if (mode == MODE_PART) {
                    float* Cz = Cf + (size_t)blockIdx.z * M * N;
                    *(float2*)(Cz + base) = make_float2(v0, v1);
                    continue;
                }

                float bv0 = __ldg(&bias[col]), bv1 = __ldg(&bias[col + 1]);
                float o0, o1;
                if (mode == MODE_RELU) {
                    o0 = fmaxf(v0 + bv0, 0.0f);
                    o1 = fmaxf(v1 + bv1, 0.0f);
                } else { // MODE_SCAN
                    float s20 = 0.f, a0 = 0.f, s21 = 0.f, a1 = 0.f;
                    float bp = beta1, wt = wt0;
                    for (int t = 0; t < T; t++) {
                        float c1m = 1.0f - bp;
                        float d0 = fmaxf(fmaf(c1m, v0, bv0), 0.0f);
                        float d1 = fmaxf(fmaf(c1m, v1, bv1), 0.0f);
                        s20 = fmaf(beta2, s20, om2 * d0);
                        s21 = fmaf(beta2, s21, om2 * d1);
                        a0 = fmaf(wt, s20, a0);
                        a1 = fmaf(wt, s21, a1);
                        bp *= beta1;
                        wt *= invb3;
                    }
                    o0 = a0; o1 = a1;
                }
                // split to bf16 hi/lo, store packed pairs
                bf16 h0 = __float2bfloat16(o0), h1 = __float2bfloat16(o1);
                bf16 l0 = __float2bfloat16(o0 - __bfloat162float(h0));
                bf16 l1 = __float2bfloat16(o1 - __bfloat162float(h1));
                uint32_t hp = (uint32_t)__bfloat16_as_ushort(h0) |
                              ((uint32_t)__bfloat16_as_ushort(h1) << 16);
                uint32_t lp = (uint32_t)__bfloat16_as_ushort(l0) |
                              ((uint32_t)__bfloat16_as_ushort(l1) << 16);
                *(uint32_t*)(OutHi + base) = hp;
                *(uint32_t*)(OutLo + base) = lp;
            }
        }
    }
}

// out[i] = (1 - beta3^T) * b3[i % N] + sum_z part[z][i]
__global__ void __launch_bounds__(256)
reduce_out(const float* __restrict__ part, const float* __restrict__ b3,
           float* __restrict__ out, int total, int N,
           const float* __restrict__ b_taus, const int* __restrict__ Tp)
{
    int i = (blockIdx.x * blockDim.x + threadIdx.x) * 4;
    if (i >= total) return;
    float beta3  = sigmoid_acc(b_taus[2]);
    float bscale = 1.0f - powf(beta3, (float)(*Tp));
    float4 bb = *(const float4*)(b3 + (i % N));
    float4 s  = make_float4(bscale * bb.x, bscale * bb.y, bscale * bb.z, bscale * bb.w);
#pragma unroll
    for (int z = 0; z < KSPLIT; z++) {
        float4 p = *(const float4*)(part + (size_t)z * total + i);
        s.x += p.x; s.y += p.y; s.z += p.z; s.w += p.w;
    }
    *(float4*)(out + i) = s;
}

extern "C" void kernel_launch(void* const* d_in, const int* in_sizes, int n_in,
                              void* d_out, int out_size)
{
    const float* x     = (const float*)d_in[0];
    const float* W1    = (const float*)d_in[1];
    const float* b1    = (const float*)d_in[2];
    const float* W2    = (const float*)d_in[3];
    const float* b2    = (const float*)d_in[4];
    const float* W3    = (const float*)d_in[5];
    const float* b3    = (const float*)d_in[6];
    const float* btaus = (const float*)d_in[7];
    const int*   Tp    = (const int*)d_in[8];

    const int H1    = in_sizes[2];
    const int D_IN  = in_sizes[1] / H1;
    const int B     = in_sizes[0] / D_IN;
    const int H2    = in_sizes[4];
    const int D_OUT = in_sizes[6];

    bf16 *xhi, *xlo, *w1hi, *w1lo, *w2hi, *w2lo, *w3hi, *w3lo;
    bf16 *d1hi, *d1lo, *s2hi, *s2lo;
    float* part;
    cudaGetSymbolAddress((void**)&xhi,  g_xhi);  cudaGetSymbolAddress((void**)&xlo,  g_xlo);
    cudaGetSymbolAddress((void**)&w1hi, g_w1hi); cudaGetSymbolAddress((void**)&w1lo, g_w1lo);
    cudaGetSymbolAddress((void**)&w2hi, g_w2hi); cudaGetSymbolAddress((void**)&w2lo, g_w2lo);
    cudaGetSymbolAddress((void**)&w3hi, g_w3hi); cudaGetSymbolAddress((void**)&w3lo, g_w3lo);
    cudaGetSymbolAddress((void**)&d1hi, g_d1hi); cudaGetSymbolAddress((void**)&d1lo, g_d1lo);
    cudaGetSymbolAddress((void**)&s2hi, g_s2hi); cudaGetSymbolAddress((void**)&s2lo, g_s2lo);
    cudaGetSymbolAddress((void**)&part, g_part);

    float* out = (float*)d_out;

    const int SMEM = 2 * 32768;
    cudaFuncSetAttribute(tc_gemm, cudaFuncAttributeMaxDynamicSharedMemorySize, SMEM);

    // 0) split inputs into bf16 hi/lo
    {
        int n;
        n = B * D_IN;   convert_split<<<n / 2048, 256>>>(x,  xhi,  xlo,  n);
        n = H1 * D_IN;  convert_split<<<n / 2048, 256>>>(W1, w1hi, w1lo, n);
        n = H2 * H1;    convert_split<<<n / 2048, 256>>>(W2, w2hi, w2lo, n);
        n = D_OUT * H2; convert_split<<<n / 2048, 256>>>(W3, w3hi, w3lo, n);
    }
    // 1) d1 = relu(x @ W1^T + b1) -> bf16 hi/lo           [B, H1]
    {
        dim3 grid(H1 / 128, B / 128, 1);
        tc_gemm<<<grid, 256, SMEM>>>(xhi, xlo, w1hi, w1lo, b1, nullptr, d1hi, d1lo,
                                     B, H1, D_IN, D_IN, MODE_RELU, btaus, Tp);
    }
    // 2) s2acc = scan(d1 @ W2^T, b2) -> bf16 hi/lo        [B, H2]
    {
        dim3 grid(H2 / 128, B / 128, 1);
        tc_gemm<<<grid, 256, SMEM>>>(d1hi, d1lo, w2hi, w2lo, b2, nullptr, s2hi, s2lo,
                                     B, H2, H1, H1, MODE_SCAN, btaus, Tp);
    }
    // 3) split-K partials of s2acc @ W3^T                 [KSPLIT][B, D_OUT]
    {
        dim3 grid(D_OUT / 128, B / 128, KSPLIT);
        tc_gemm<<<grid, 256, SMEM>>>(s2hi, s2lo, w3hi, w3lo, nullptr, part, nullptr, nullptr,
                                     B, D_OUT, H2 / KSPLIT, H2, MODE_PART, btaus, Tp);
    }
    // 4) out = (1-b3^T) b3 + sum partials                 [B, D_OUT]
    {
        int total = B * D_OUT;
        reduce_out<<<(total / 4 + 255) / 256, 256>>>(part, b3, out, total, D_OUT, btaus, Tp);
    }
    (void)n_in; (void)out_size;
}